// round 4
// baseline (speedup 1.0000x reference)
#include <cuda_runtime.h>

#define BATCH 4
#define KTGT  64

// ---------------- device-global scratch (no allocations allowed) ----------
__device__ float4   g_tgt[BATCH][KTGT];     // compacted, masked targets (pad=1e18)
__device__ int      g_cnt[BATCH];           // n_valid per batch
__device__ unsigned g_g2p[BATCH][KTGT];     // min ld^2 per (b,k), as ordered u32 bits
__device__ float    g_dist[BATCH];
__device__ float    g_p2g[BATCH];
__device__ float    g_sep[BATCH];

// ---------------- kernel 1: mask/compact targets + zero accumulators ------
__global__ void k_init(const float* __restrict__ tC,
                       const int*   __restrict__ tF,
                       const int*   __restrict__ classes, int nclass)
{
    int tid = threadIdx.x;
    if (tid < BATCH) { g_dist[tid] = 0.f; g_p2g[tid] = 0.f; g_sep[tid] = 0.f; }
    if (tid < BATCH * KTGT) ((unsigned*)g_g2p)[tid] = 0x7f800000u;  // +inf bits

    int w = tid >> 5, lane = tid & 31;
    if (w < BATCH) {
        int cnt = 0;
        #pragma unroll
        for (int half = 0; half < 2; half++) {
            int k = lane + 32 * half;
            int c = tF[w * KTGT + k];
            bool m = false;
            for (int j = 0; j < nclass; j++) m |= (c == __ldg(&classes[j]));
            unsigned bal = __ballot_sync(0xffffffffu, m);
            int pos = cnt + __popc(bal & ((1u << lane) - 1u));
            if (m) {
                const float* p = tC + (w * KTGT + k) * 3;
                g_tgt[w][pos] = make_float4(p[0], p[1], p[2], 0.f);
            }
            cnt += __popc(bal);
        }
        if (lane == 0) g_cnt[w] = cnt;
        for (int k = cnt + lane; k < KTGT; k += 32)
            g_tgt[w][k] = make_float4(1e18f, 1e18f, 1e18f, 0.f);
    }
}

// ---------------- kernel 2: main O(N*K) pass ------------------------------
__global__ void __launch_bounds__(256) k_main(const float* __restrict__ lC,
                                              const float* __restrict__ lF,
                                              int N)
{
    const int b    = blockIdx.y;
    const int tid  = threadIdx.x;
    const int lane = tid & 31;
    const int n    = blockIdx.x * 256 + tid;

    __shared__ float4   s_t[KTGT];
    __shared__ unsigned s_g2p[KTGT];
    __shared__ float    s_red[24];

    if (tid < KTGT) { s_t[tid] = g_tgt[b][tid]; s_g2p[tid] = 0x7f800000u; }
    __syncthreads();

    const int  cnt4  = (g_cnt[b] + 3) & ~3;
    const bool valid = (n < N);

    float cx, cy, cz, d0, fx2, fy2, fz2, f2;
    if (valid) {
        const float* pc = lC + ((size_t)b * N + n) * 3;
        cx = pc[0]; cy = pc[1]; cz = pc[2];
        float4 f = reinterpret_cast<const float4*>(lF)[(size_t)b * N + n];
        d0  = f.x;
        fx2 = 2.f * f.y; fy2 = 2.f * f.z; fz2 = 2.f * f.w;
        f2  = f.y * f.y + f.z * f.z + f.w * f.w;
    } else {
        // far away: contributes only huge values to all mins; dist term masked below
        cx = 1e18f; cy = 0.f; cz = 0.f; d0 = 0.f;
        fx2 = fy2 = fz2 = 0.f; f2 = 0.f;
    }

    float best = 3e38f, second = 3e38f;   // two smallest masked pd^2
    float l2b  = 3e38f, l2s    = 3e38f;   // ld^2 carried at those argmins
    float l2min = 3e38f;                  // min ld^2 (p2g, squared)

    #pragma unroll 4
    for (int k = 0; k < cnt4; k++) {
        float4 t  = s_t[k];                       // LDS.128 broadcast
        float dx  = cx - t.x, dy = cy - t.y, dz = cz - t.z;
        float pd2 = fmaf(dx, dx, fmaf(dy, dy, dz * dz));
        float s   = fmaf(dx, fx2, fmaf(dy, fy2, fmaf(dz, fz2, f2)));
        float ld2 = fmaxf(pd2 + s, 0.f);          // ||C+F'-t||^2, clamped >=0

        l2min = fminf(l2min, ld2);

        bool pb = pd2 < best;
        bool ps = pd2 < second;
        second  = pb ? best : (ps ? pd2 : second);
        l2s     = pb ? l2b  : (ps ? ld2 : l2s);
        best    = pb ? pd2  : best;
        l2b     = pb ? ld2  : l2b;

        // per-target min over landmarks (g2p), u32-ordered for non-negative floats
        unsigned red = __reduce_min_sync(0xffffffffu, __float_as_uint(ld2));
        if (lane == (k & 31)) atomicMin(&s_g2p[k], red);
    }

    float mind = sqrtf(best);
    bool  pm   = mind < 0.1f;
    float tgt  = fminf(mind, 0.2f);
    float diff = d0 - tgt;
    float ad   = fabsf(diff);
    float dl   = (ad < 1.f) ? 0.5f * diff * diff : (ad - 0.5f);
    dl         = valid ? dl : 0.f;
    float p2g2 = pm ? l2min : 0.f;                          // pm => valid
    float sep  = pm ? sqrtf(__fdividef(l2b, l2s)) : 0.f;    // ld(nn1)/ld(nn2)

    // block reduction of the three sums
    #pragma unroll
    for (int o = 16; o > 0; o >>= 1) {
        dl   += __shfl_down_sync(0xffffffffu, dl,   o);
        p2g2 += __shfl_down_sync(0xffffffffu, p2g2, o);
        sep  += __shfl_down_sync(0xffffffffu, sep,  o);
    }
    int wid = tid >> 5;
    if (lane == 0) { s_red[wid] = dl; s_red[8 + wid] = p2g2; s_red[16 + wid] = sep; }
    __syncthreads();

    if (tid < KTGT) atomicMin(&g_g2p[b][tid], s_g2p[tid]);
    if (tid == 0) {
        float a0 = 0.f, a1 = 0.f, a2 = 0.f;
        #pragma unroll
        for (int i = 0; i < 8; i++) { a0 += s_red[i]; a1 += s_red[8 + i]; a2 += s_red[16 + i]; }
        atomicAdd(&g_dist[b], a0);
        atomicAdd(&g_p2g[b],  a1);
        atomicAdd(&g_sep[b],  a2);
    }
}

// ---------------- kernel 3: combine ---------------------------------------
__global__ void k_final(float* __restrict__ out)
{
    __shared__ float s[BATCH * KTGT];
    int tid = threadIdx.x;                 // 256 threads
    int b = tid >> 6, k = tid & 63;
    float v = (k < g_cnt[b]) ? __uint_as_float(g_g2p[b][k]) : 0.f;
    s[tid] = v;
    __syncthreads();
    #pragma unroll
    for (int o = 32; o > 0; o >>= 1) {
        if (k < o) s[tid] += s[tid + o];
        __syncthreads();
    }
    if (tid == 0) {
        float acc = 0.f;
        for (int bb = 0; bb < BATCH; bb++) {
            float g2p2 = s[bb * 64];
            float loss = 0.05f * g_dist[bb]
                       + 0.05f * (g_p2g[bb] + g2p2)
                       + 0.0005f * ((g_cnt[bb] >= 2) ? g_sep[bb] : 0.f);
            acc += loss;
        }
        out[0] = acc * (1.f / BATCH);
    }
}

// ---------------- launch ---------------------------------------------------
extern "C" void kernel_launch(void* const* d_in, const int* in_sizes, int n_in,
                              void* d_out, int out_size)
{
    const float* lC      = (const float*)d_in[0];
    const float* lF      = (const float*)d_in[1];
    const float* tC      = (const float*)d_in[2];
    const int*   tF      = (const int*)d_in[3];
    const int*   classes = (const int*)d_in[4];
    int nclass = in_sizes[4];
    int N      = in_sizes[0] / (BATCH * 3);

    k_init<<<1, 256>>>(tC, tF, classes, nclass);
    dim3 grid((N + 255) / 256, BATCH);
    k_main<<<grid, 256>>>(lC, lF, N);
    k_final<<<1, 256>>>((float*)d_out);
}

// round 5
// speedup vs baseline: 1.5101x; 1.5101x over previous
#include <cuda_runtime.h>

#define BATCH 4
#define KTGT  64
#define L     4                 // landmarks per thread
#define TPB   256
#define TILE  (TPB * L)

// ------------- statically-initialized device scratch (no allocs) ----------
#define I8  0x7f800000u,0x7f800000u,0x7f800000u,0x7f800000u,0x7f800000u,0x7f800000u,0x7f800000u,0x7f800000u
#define I64 I8,I8,I8,I8,I8,I8,I8,I8
__device__ unsigned g_g2p[BATCH * KTGT] = { I64, I64, I64, I64 }; // +inf bits
__device__ int      g_cnt[BATCH];                                  // zero-init
__device__ float    g_dist[BATCH], g_p2g[BATCH], g_sep[BATCH];     // zero-init

// ---------------- kernel 1: fused compaction + main O(N*K) pass -----------
__global__ void __launch_bounds__(TPB, 2) k_main(
    const float* __restrict__ lC, const float* __restrict__ lF,
    const float* __restrict__ tC, const int* __restrict__ tF,
    const int* __restrict__ classes, int nclass, int N)
{
    const int b    = blockIdx.y;
    const int tid  = threadIdx.x;
    const int lane = tid & 31;
    const int base = blockIdx.x * TILE;

    __shared__ float4   s_t[KTGT];
    __shared__ unsigned s_g2p[KTGT];
    __shared__ int      s_cnt;
    __shared__ float    s_red[24];

    // ---- landmark loads first: LDG latency overlaps the compaction below
    float cx[L], cy[L], cz[L], d0[L], fx2[L], fy2[L], fz2[L], f2[L];
    bool  val[L];
    #pragma unroll
    for (int i = 0; i < L; i++) {
        int n  = base + tid + i * TPB;
        val[i] = (n < N);
        if (val[i]) {
            const float* pc = lC + ((size_t)b * N + n) * 3;
            cx[i] = pc[0]; cy[i] = pc[1]; cz[i] = pc[2];
            float4 f = reinterpret_cast<const float4*>(lF)[(size_t)b * N + n];
            d0[i]  = f.x;
            fx2[i] = 2.f * f.y; fy2[i] = 2.f * f.z; fz2[i] = 2.f * f.w;
            f2[i]  = f.y * f.y + f.z * f.z + f.w * f.w;
        } else {
            cx[i] = 1e18f; cy[i] = 0.f; cz[i] = 0.f; d0[i] = 0.f;
            fx2[i] = fy2[i] = fz2[i] = 0.f; f2[i] = 0.f;
        }
    }

    // ---- per-block target compaction (warp 0), padding to 1e18
    if (tid < KTGT) s_g2p[tid] = 0x7f800000u;
    if (tid < 32) {
        int cnt = 0;
        #pragma unroll
        for (int half = 0; half < 2; half++) {
            int k = lane + 32 * half;
            int c = tF[b * KTGT + k];
            bool m = false;
            for (int j = 0; j < nclass; j++) m |= (c == __ldg(&classes[j]));
            unsigned bal = __ballot_sync(0xffffffffu, m);
            int pos = cnt + __popc(bal & ((1u << lane) - 1u));
            if (m) {
                const float* p = tC + (b * KTGT + k) * 3;
                s_t[pos] = make_float4(p[0], p[1], p[2], 0.f);
            }
            cnt += __popc(bal);
        }
        for (int k = cnt + lane; k < KTGT; k += 32)
            s_t[k] = make_float4(1e18f, 1e18f, 1e18f, 0.f);
        if (lane == 0) { s_cnt = cnt; if (blockIdx.x == 0) g_cnt[b] = cnt; }
    }
    __syncthreads();
    const int cnt = s_cnt;

    // ---- trackers: packed u32 keys (pd2 hi-bits | k), two smallest via IMNMX
    unsigned bk[L], sk[L];
    float    lmin[L];
    #pragma unroll
    for (int i = 0; i < L; i++) { bk[i] = 0xFFFFFFFFu; sk[i] = 0xFFFFFFFFu; lmin[i] = 3e38f; }
    unsigned r0 = 0x7f800000u, r1 = 0x7f800000u;   // per-warp g2p mins (k<32, k>=32)

    auto body = [&](int k, unsigned& r, int lsh) {
        float4 t  = s_t[k];                               // LDS.128 broadcast
        float  m4 = 3e38f;
        #pragma unroll
        for (int i = 0; i < L; i++) {
            float dx  = cx[i] - t.x, dy = cy[i] - t.y, dz = cz[i] - t.z;
            float pd2 = fmaf(dx, dx, fmaf(dy, dy, dz * dz));
            float s   = fmaf(dx, fx2[i], fmaf(dy, fy2[i], fmaf(dz, fz2[i], f2[i])));
            float ld2 = fmaxf(pd2 + s, 0.f);
            lmin[i]   = fminf(lmin[i], ld2);
            m4        = fminf(m4, ld2);
            unsigned key = (__float_as_uint(pd2) & 0xFFFFFFC0u) | (unsigned)k;
            unsigned tmx = max(key, bk[i]);               // old best
            sk[i] = min(sk[i], tmx);
            bk[i] = min(bk[i], key);
        }
        unsigned red = __reduce_min_sync(0xffffffffu, __float_as_uint(m4));
        if (lane == k - lsh) r = min(r, red);
    };

    int kend0 = (cnt < 32) ? cnt : 32;
    int k = 0;
    #pragma unroll 4
    for (; k < kend0; k++) body(k, r0, 0);
    #pragma unroll 4
    for (; k < cnt;   k++) body(k, r1, 32);

    // merge per-warp g2p mins into shared (spread-address shared atomics)
    atomicMin(&s_g2p[lane],      r0);
    atomicMin(&s_g2p[lane + 32], r1);

    // ---- post-loop: recover ld2 at nn1/nn2, finish per-landmark terms
    auto ld2_at = [&](int i, float4 t) {
        float dx  = cx[i] - t.x, dy = cy[i] - t.y, dz = cz[i] - t.z;
        float pd2 = fmaf(dx, dx, fmaf(dy, dy, dz * dz));
        float s   = fmaf(dx, fx2[i], fmaf(dy, fy2[i], fmaf(dz, fz2[i], f2[i])));
        return fmaxf(pd2 + s, 0.f);
    };

    float dl = 0.f, p2g2 = 0.f, sep = 0.f;
    #pragma unroll
    for (int i = 0; i < L; i++) {
        float pd2b = __uint_as_float(bk[i] & 0xFFFFFFC0u);
        float mind = sqrtf(pd2b);
        bool  pm   = mind < 0.1f;
        float tgt  = fminf(mind, 0.2f);
        float diff = d0[i] - tgt;
        float ad   = fabsf(diff);
        float h    = (ad < 1.f) ? 0.5f * diff * diff : (ad - 0.5f);
        dl += val[i] ? h : 0.f;
        if (pm) {                                        // pm => valid landmark
            float l1 = ld2_at(i, s_t[bk[i] & 63u]);
            float l2 = ld2_at(i, s_t[sk[i] & 63u]);
            p2g2 += lmin[i];
            sep  += sqrtf(__fdividef(l1, l2));           // ld(nn1)/ld(nn2)
        }
    }

    // ---- block reduction of the three sums
    #pragma unroll
    for (int o = 16; o > 0; o >>= 1) {
        dl   += __shfl_down_sync(0xffffffffu, dl,   o);
        p2g2 += __shfl_down_sync(0xffffffffu, p2g2, o);
        sep  += __shfl_down_sync(0xffffffffu, sep,  o);
    }
    int wid = tid >> 5;
    if (lane == 0) { s_red[wid] = dl; s_red[8 + wid] = p2g2; s_red[16 + wid] = sep; }
    __syncthreads();

    if (tid < KTGT) atomicMin(&g_g2p[b * KTGT + tid], s_g2p[tid]);
    if (tid == 0) {
        float a0 = 0.f, a1 = 0.f, a2 = 0.f;
        #pragma unroll
        for (int i = 0; i < 8; i++) { a0 += s_red[i]; a1 += s_red[8 + i]; a2 += s_red[16 + i]; }
        atomicAdd(&g_dist[b], a0);
        atomicAdd(&g_p2g[b],  a1);
        atomicAdd(&g_sep[b],  a2);
    }
}

// ---------------- kernel 2: combine + restore pristine scratch ------------
__global__ void k_final(float* __restrict__ out)
{
    __shared__ float s[BATCH * KTGT];
    int tid = threadIdx.x;                 // 256 threads
    int b = tid >> 6, k = tid & 63;
    int cnt = g_cnt[b];
    float v = (k < cnt) ? __uint_as_float(g_g2p[tid]) : 0.f;
    s[tid] = v;
    __syncthreads();
    #pragma unroll
    for (int o = 32; o > 0; o >>= 1) {
        if (k < o) s[tid] += s[tid + o];
        __syncthreads();
    }
    if (tid == 0) {
        float acc = 0.f;
        for (int bb = 0; bb < BATCH; bb++) {
            acc += 0.05f * g_dist[bb]
                 + 0.05f * (g_p2g[bb] + s[bb * 64])
                 + 0.0005f * ((g_cnt[bb] >= 2) ? g_sep[bb] : 0.f);
        }
        out[0] = acc * (1.f / BATCH);
        // restore pristine accumulators for the next graph replay
        #pragma unroll
        for (int bb = 0; bb < BATCH; bb++) { g_dist[bb] = 0.f; g_p2g[bb] = 0.f; g_sep[bb] = 0.f; }
    }
    g_g2p[tid] = 0x7f800000u;              // own element, already consumed
}

// ---------------- launch ---------------------------------------------------
extern "C" void kernel_launch(void* const* d_in, const int* in_sizes, int n_in,
                              void* d_out, int out_size)
{
    const float* lC      = (const float*)d_in[0];
    const float* lF      = (const float*)d_in[1];
    const float* tC      = (const float*)d_in[2];
    const int*   tF      = (const int*)d_in[3];
    const int*   classes = (const int*)d_in[4];
    int nclass = in_sizes[4];
    int N      = in_sizes[0] / (BATCH * 3);

    dim3 grid((N + TILE - 1) / TILE, BATCH);
    k_main<<<grid, TPB>>>(lC, lF, tC, tF, classes, nclass, N);
    k_final<<<1, 256>>>((float*)d_out);
}

// round 6
// speedup vs baseline: 1.5753x; 1.0431x over previous
#include <cuda_runtime.h>

#define BATCH 4
#define KTGT  64
#define L     4                 // landmarks per thread (2 f32x2 pairs)
#define TPB   256
#define TILE  (TPB * L)

typedef unsigned long long u64;

// ------------- statically-initialized device scratch (no allocs) ----------
#define I8  0x7f800000u,0x7f800000u,0x7f800000u,0x7f800000u,0x7f800000u,0x7f800000u,0x7f800000u,0x7f800000u
#define I64 I8,I8,I8,I8,I8,I8,I8,I8
__device__ unsigned g_g2p[BATCH * KTGT] = { I64, I64, I64, I64 }; // +inf bits
__device__ int      g_cnt[BATCH];
__device__ float    g_dist[BATCH], g_p2g[BATCH], g_sep[BATCH];
__device__ unsigned g_ticket;                                      // zero-init

// ------------- f32x2 packed-math helpers (Blackwell FFMA2 path) -----------
__device__ __forceinline__ u64 pk2(float a, float b) {
    u64 d; asm("mov.b64 %0, {%1, %2};" : "=l"(d) : "f"(a), "f"(b)); return d;
}
__device__ __forceinline__ void upk2(float& a, float& b, u64 d) {
    asm("mov.b64 {%0, %1}, %2;" : "=f"(a), "=f"(b) : "l"(d));
}
__device__ __forceinline__ u64 add2(u64 a, u64 b) {
    u64 d; asm("add.rn.f32x2 %0, %1, %2;" : "=l"(d) : "l"(a), "l"(b)); return d;
}
__device__ __forceinline__ u64 mul2(u64 a, u64 b) {
    u64 d; asm("mul.rn.f32x2 %0, %1, %2;" : "=l"(d) : "l"(a), "l"(b)); return d;
}
__device__ __forceinline__ u64 fma2(u64 a, u64 b, u64 c) {
    u64 d; asm("fma.rn.f32x2 %0, %1, %2, %3;" : "=l"(d) : "l"(a), "l"(b), "l"(c)); return d;
}
__device__ __forceinline__ float half_of(u64 d, int h) {
    float a, b; upk2(a, b, d); return h ? b : a;
}

// ---------------- single fused kernel --------------------------------------
__global__ void __launch_bounds__(TPB, 2) k_main(
    const float* __restrict__ lC, const float* __restrict__ lF,
    const float* __restrict__ tC, const int* __restrict__ tF,
    const int* __restrict__ classes, int nclass, int N,
    float* __restrict__ out)
{
    const int b    = blockIdx.y;
    const int tid  = threadIdx.x;
    const int lane = tid & 31;
    const int base = blockIdx.x * TILE;

    __shared__ u64      s_tp[KTGT * 3];     // negated, duplicated targets (f32x2)
    __shared__ unsigned s_g2p[KTGT];
    __shared__ int      s_cnt;
    __shared__ float    s_red[24];
    __shared__ float    s_fin[BATCH * KTGT];
    __shared__ unsigned s_last;

    // ---- landmark loads (LDG latency overlaps compaction below)
    float cxs[L], cys[L], czs[L], d0[L], fxs[L], fys[L], fzs[L], f2s[L];
    bool  val[L];
    #pragma unroll
    for (int i = 0; i < L; i++) {
        int n  = base + tid + i * TPB;
        val[i] = (n < N);
        if (val[i]) {
            const float* pc = lC + ((size_t)b * N + n) * 3;
            cxs[i] = pc[0]; cys[i] = pc[1]; czs[i] = pc[2];
            float4 f = reinterpret_cast<const float4*>(lF)[(size_t)b * N + n];
            d0[i]  = f.x;
            fxs[i] = 2.f * f.y; fys[i] = 2.f * f.z; fzs[i] = 2.f * f.w;
            f2s[i] = f.y * f.y + f.z * f.z + f.w * f.w;
        } else {
            cxs[i] = 1e18f; cys[i] = 0.f; czs[i] = 0.f; d0[i] = 0.f;
            fxs[i] = fys[i] = fzs[i] = 0.f; f2s[i] = 0.f;
        }
    }
    // pack into f32x2 pairs: pair p = landmarks (2p, 2p+1)
    u64 cx2[2], cy2[2], cz2[2], fxx[2], fyy[2], fzz[2], ff2[2];
    #pragma unroll
    for (int p = 0; p < 2; p++) {
        cx2[p] = pk2(cxs[2*p], cxs[2*p+1]);
        cy2[p] = pk2(cys[2*p], cys[2*p+1]);
        cz2[p] = pk2(czs[2*p], czs[2*p+1]);
        fxx[p] = pk2(fxs[2*p], fxs[2*p+1]);
        fyy[p] = pk2(fys[2*p], fys[2*p+1]);
        fzz[p] = pk2(fzs[2*p], fzs[2*p+1]);
        ff2[p] = pk2(f2s[2*p], f2s[2*p+1]);
    }

    // ---- per-block target compaction (warp 0); store negated+duplicated
    if (tid < KTGT) s_g2p[tid] = 0x7f800000u;
    if (tid < 32) {
        int cnt = 0;
        #pragma unroll
        for (int half = 0; half < 2; half++) {
            int k = lane + 32 * half;
            int c = tF[b * KTGT + k];
            bool m = false;
            for (int j = 0; j < nclass; j++) m |= (c == __ldg(&classes[j]));
            unsigned bal = __ballot_sync(0xffffffffu, m);
            int pos = cnt + __popc(bal & ((1u << lane) - 1u));
            if (m) {
                const float* p = tC + (b * KTGT + k) * 3;
                float x = -p[0], y = -p[1], z = -p[2];
                s_tp[pos * 3 + 0] = pk2(x, x);
                s_tp[pos * 3 + 1] = pk2(y, y);
                s_tp[pos * 3 + 2] = pk2(z, z);
            }
            cnt += __popc(bal);
        }
        u64 pad = pk2(-1e18f, -1e18f);
        for (int k = cnt + lane; k < KTGT; k += 32) {
            s_tp[k * 3 + 0] = pad; s_tp[k * 3 + 1] = pad; s_tp[k * 3 + 2] = pad;
        }
        if (lane == 0) { s_cnt = cnt; if (blockIdx.x == 0) g_cnt[b] = cnt; }
    }
    __syncthreads();
    const int cnt = s_cnt;

    // ---- trackers
    unsigned bk[L], sk[L];
    float    lmin[L];
    #pragma unroll
    for (int i = 0; i < L; i++) { bk[i] = 0xFFFFFFFFu; sk[i] = 0xFFFFFFFFu; lmin[i] = 3e38f; }
    unsigned r0 = 0x7f800000u, r1 = 0x7f800000u;

    auto body = [&](int k, unsigned& r, int lsh) {
        u64 ntx = s_tp[k * 3 + 0];           // LDS.64 broadcast
        u64 nty = s_tp[k * 3 + 1];
        u64 ntz = s_tp[k * 3 + 2];
        float m4 = 3e38f;
        #pragma unroll
        for (int p = 0; p < 2; p++) {
            u64 dx = add2(cx2[p], ntx);
            u64 dy = add2(cy2[p], nty);
            u64 dz = add2(cz2[p], ntz);
            u64 pd2 = mul2(dz, dz);
            pd2 = fma2(dy, dy, pd2);
            pd2 = fma2(dx, dx, pd2);
            u64 sc = fma2(dz, fzz[p], ff2[p]);
            sc = fma2(dy, fyy[p], sc);
            sc = fma2(dx, fxx[p], sc);
            u64 l2 = add2(pd2, sc);
            float pa, pb, la, lb;
            upk2(pa, pb, pd2);
            upk2(la, lb, l2);
            la = fmaxf(la, 0.f); lb = fmaxf(lb, 0.f);
            lmin[2*p]   = fminf(lmin[2*p],   la);
            lmin[2*p+1] = fminf(lmin[2*p+1], lb);
            m4 = fminf(m4, fminf(la, lb));
            unsigned ka = (__float_as_uint(pa) & 0xFFFFFFC0u) | (unsigned)k;
            unsigned kb = (__float_as_uint(pb) & 0xFFFFFFC0u) | (unsigned)k;
            unsigned ta = max(ka, bk[2*p]);
            sk[2*p]   = min(sk[2*p], ta);
            bk[2*p]   = min(bk[2*p], ka);
            unsigned tb = max(kb, bk[2*p+1]);
            sk[2*p+1] = min(sk[2*p+1], tb);
            bk[2*p+1] = min(bk[2*p+1], kb);
        }
        unsigned red = __reduce_min_sync(0xffffffffu, __float_as_uint(m4));
        if (lane == k - lsh) r = min(r, red);
    };

    int kend0 = (cnt < 32) ? cnt : 32;
    int k = 0;
    #pragma unroll 4
    for (; k < kend0; k++) body(k, r0, 0);
    #pragma unroll 4
    for (; k < cnt;   k++) body(k, r1, 32);

    atomicMin(&s_g2p[lane],      r0);
    atomicMin(&s_g2p[lane + 32], r1);

    // ---- post-loop: recover ld2 at nn1/nn2 (only for pm landmarks)
    auto ld2_at = [&](int i, int kk) -> float {
        int p = i >> 1, h = i & 1;
        float tx = half_of(s_tp[kk * 3 + 0], 0);  // negated target
        float ty = half_of(s_tp[kk * 3 + 1], 0);
        float tz = half_of(s_tp[kk * 3 + 2], 0);
        float dx = half_of(cx2[p], h) + tx;
        float dy = half_of(cy2[p], h) + ty;
        float dz = half_of(cz2[p], h) + tz;
        float pd2 = fmaf(dx, dx, fmaf(dy, dy, dz * dz));
        float s   = fmaf(dx, half_of(fxx[p], h),
                    fmaf(dy, half_of(fyy[p], h),
                    fmaf(dz, half_of(fzz[p], h), half_of(ff2[p], h))));
        return fmaxf(pd2 + s, 0.f);
    };

    float dl = 0.f, p2g2 = 0.f, sep = 0.f;
    #pragma unroll
    for (int i = 0; i < L; i++) {
        float pd2b = __uint_as_float(bk[i] & 0xFFFFFFC0u);
        float mind = sqrtf(pd2b);
        bool  pm   = mind < 0.1f;
        float tgt  = fminf(mind, 0.2f);
        float diff = d0[i] - tgt;
        float ad   = fabsf(diff);
        float h    = (ad < 1.f) ? 0.5f * diff * diff : (ad - 0.5f);
        dl += val[i] ? h : 0.f;
        if (pm) {
            float l1 = ld2_at(i, (int)(bk[i] & 63u));
            float l2 = ld2_at(i, (int)(sk[i] & 63u));
            p2g2 += lmin[i];
            sep  += sqrtf(__fdividef(l1, l2));
        }
    }

    // ---- block reduction
    #pragma unroll
    for (int o = 16; o > 0; o >>= 1) {
        dl   += __shfl_down_sync(0xffffffffu, dl,   o);
        p2g2 += __shfl_down_sync(0xffffffffu, p2g2, o);
        sep  += __shfl_down_sync(0xffffffffu, sep,  o);
    }
    int wid = tid >> 5;
    if (lane == 0) { s_red[wid] = dl; s_red[8 + wid] = p2g2; s_red[16 + wid] = sep; }
    __syncthreads();

    if (tid < KTGT) atomicMin(&g_g2p[b * KTGT + tid], s_g2p[tid]);
    if (tid == 0) {
        float a0 = 0.f, a1 = 0.f, a2 = 0.f;
        #pragma unroll
        for (int i = 0; i < 8; i++) { a0 += s_red[i]; a1 += s_red[8 + i]; a2 += s_red[16 + i]; }
        atomicAdd(&g_dist[b], a0);
        atomicAdd(&g_p2g[b],  a1);
        atomicAdd(&g_sep[b],  a2);
    }

    // ---- last-block finalize (replaces the separate 5.2us k_final launch)
    __threadfence();
    if (tid == 0) s_last = atomicAdd(&g_ticket, 1u);
    __syncthreads();
    if (s_last == gridDim.x * gridDim.y - 1u) {
        int bb = tid >> 6, kk = tid & 63;
        s_fin[tid] = (kk < g_cnt[bb]) ? __uint_as_float(g_g2p[tid]) : 0.f;
        __syncthreads();
        #pragma unroll
        for (int o = 32; o > 0; o >>= 1) {
            if (kk < o) s_fin[tid] += s_fin[tid + o];
            __syncthreads();
        }
        if (tid == 0) {
            float acc = 0.f;
            #pragma unroll
            for (int bb2 = 0; bb2 < BATCH; bb2++) {
                acc += 0.05f * g_dist[bb2]
                     + 0.05f * (g_p2g[bb2] + s_fin[bb2 * 64])
                     + 0.0005f * ((g_cnt[bb2] >= 2) ? g_sep[bb2] : 0.f);
                g_dist[bb2] = 0.f; g_p2g[bb2] = 0.f; g_sep[bb2] = 0.f;
            }
            out[0] = acc * (1.f / BATCH);
            g_ticket = 0;
        }
        g_g2p[tid] = 0x7f800000u;          // restore pristine for next replay
    }
}

// ---------------- launch ---------------------------------------------------
extern "C" void kernel_launch(void* const* d_in, const int* in_sizes, int n_in,
                              void* d_out, int out_size)
{
    const float* lC      = (const float*)d_in[0];
    const float* lF      = (const float*)d_in[1];
    const float* tC      = (const float*)d_in[2];
    const int*   tF      = (const int*)d_in[3];
    const int*   classes = (const int*)d_in[4];
    int nclass = in_sizes[4];
    int N      = in_sizes[0] / (BATCH * 3);

    dim3 grid((N + TILE - 1) / TILE, BATCH);
    k_main<<<grid, TPB>>>(lC, lF, tC, tF, classes, nclass, N, (float*)d_out);
}

// round 7
// speedup vs baseline: 1.7379x; 1.1032x over previous
#include <cuda_runtime.h>

#define BATCH 4
#define KTGT  64
#define L     4                 // landmarks per thread (2 f32x2 pairs)
#define TPB   256
#define TILE  (TPB * L)

typedef unsigned long long u64;

// ------------- statically-initialized device scratch (no allocs) ----------
#define I8  0x7f800000u,0x7f800000u,0x7f800000u,0x7f800000u,0x7f800000u,0x7f800000u,0x7f800000u,0x7f800000u
#define I64 I8,I8,I8,I8,I8,I8,I8,I8
__device__ unsigned g_g2p[BATCH * KTGT] = { I64, I64, I64, I64 }; // +inf bits
__device__ int      g_cnt[BATCH];
__device__ float    g_dist[BATCH], g_p2g[BATCH], g_sep[BATCH];
__device__ unsigned g_ticket;                                      // zero-init

// ------------- f32x2 packed-math helpers (Blackwell FFMA2 path) -----------
__device__ __forceinline__ u64 pk2(float a, float b) {
    u64 d; asm("mov.b64 %0, {%1, %2};" : "=l"(d) : "f"(a), "f"(b)); return d;
}
__device__ __forceinline__ void upk2(float& a, float& b, u64 d) {
    asm("mov.b64 {%0, %1}, %2;" : "=f"(a), "=f"(b) : "l"(d));
}
__device__ __forceinline__ u64 add2(u64 a, u64 b) {
    u64 d; asm("add.rn.f32x2 %0, %1, %2;" : "=l"(d) : "l"(a), "l"(b)); return d;
}
__device__ __forceinline__ u64 mul2(u64 a, u64 b) {
    u64 d; asm("mul.rn.f32x2 %0, %1, %2;" : "=l"(d) : "l"(a), "l"(b)); return d;
}
__device__ __forceinline__ u64 fma2(u64 a, u64 b, u64 c) {
    u64 d; asm("fma.rn.f32x2 %0, %1, %2, %3;" : "=l"(d) : "l"(a), "l"(b), "l"(c)); return d;
}
__device__ __forceinline__ float half_of(u64 d, int h) {
    float a, b; upk2(a, b, d); return h ? b : a;
}

// ---------------- single fused kernel --------------------------------------
__global__ void __launch_bounds__(TPB, 3) k_main(
    const float* __restrict__ lC, const float* __restrict__ lF,
    const float* __restrict__ tC, const int* __restrict__ tF,
    const int* __restrict__ classes, int nclass, int N,
    float* __restrict__ out)
{
    const int b    = blockIdx.y;
    const int tid  = threadIdx.x;
    const int lane = tid & 31;
    const int base = blockIdx.x * TILE;

    __shared__ u64      s_tp[KTGT * 3];     // negated, duplicated targets (f32x2)
    __shared__ unsigned s_g2p[KTGT];
    __shared__ int      s_cnt;
    __shared__ float    s_red[24];
    __shared__ float    s_fin[BATCH * KTGT];
    __shared__ unsigned s_last;

    // ---- landmark loads (LDG latency overlaps compaction below)
    float cxs[L], cys[L], czs[L], d0[L], fxs[L], fys[L], fzs[L], f2s[L];
    bool  val[L];
    #pragma unroll
    for (int i = 0; i < L; i++) {
        int n  = base + tid + i * TPB;
        val[i] = (n < N);
        if (val[i]) {
            const float* pc = lC + ((size_t)b * N + n) * 3;
            cxs[i] = pc[0]; cys[i] = pc[1]; czs[i] = pc[2];
            float4 f = reinterpret_cast<const float4*>(lF)[(size_t)b * N + n];
            d0[i]  = f.x;
            fxs[i] = 2.f * f.y; fys[i] = 2.f * f.z; fzs[i] = 2.f * f.w;
            f2s[i] = f.y * f.y + f.z * f.z + f.w * f.w;
        } else {
            cxs[i] = 1e18f; cys[i] = 0.f; czs[i] = 0.f; d0[i] = 0.f;
            fxs[i] = fys[i] = fzs[i] = 0.f; f2s[i] = 0.f;
        }
    }
    // pack into f32x2 pairs: pair p = landmarks (2p, 2p+1)
    u64 cx2[2], cy2[2], cz2[2], fxx[2], fyy[2], fzz[2], ff2[2];
    #pragma unroll
    for (int p = 0; p < 2; p++) {
        cx2[p] = pk2(cxs[2*p], cxs[2*p+1]);
        cy2[p] = pk2(cys[2*p], cys[2*p+1]);
        cz2[p] = pk2(czs[2*p], czs[2*p+1]);
        fxx[p] = pk2(fxs[2*p], fxs[2*p+1]);
        fyy[p] = pk2(fys[2*p], fys[2*p+1]);
        fzz[p] = pk2(fzs[2*p], fzs[2*p+1]);
        ff2[p] = pk2(f2s[2*p], f2s[2*p+1]);
    }

    // ---- per-block target compaction (warp 0); store negated+duplicated
    if (tid < KTGT) s_g2p[tid] = 0x7f800000u;
    if (tid < 32) {
        int cnt = 0;
        #pragma unroll
        for (int half = 0; half < 2; half++) {
            int k = lane + 32 * half;
            int c = tF[b * KTGT + k];
            bool m = false;
            for (int j = 0; j < nclass; j++) m |= (c == __ldg(&classes[j]));
            unsigned bal = __ballot_sync(0xffffffffu, m);
            int pos = cnt + __popc(bal & ((1u << lane) - 1u));
            if (m) {
                const float* p = tC + (b * KTGT + k) * 3;
                float x = -p[0], y = -p[1], z = -p[2];
                s_tp[pos * 3 + 0] = pk2(x, x);
                s_tp[pos * 3 + 1] = pk2(y, y);
                s_tp[pos * 3 + 2] = pk2(z, z);
            }
            cnt += __popc(bal);
        }
        u64 pad = pk2(-1e18f, -1e18f);
        for (int k = cnt + lane; k < KTGT; k += 32) {
            s_tp[k * 3 + 0] = pad; s_tp[k * 3 + 1] = pad; s_tp[k * 3 + 2] = pad;
        }
        if (lane == 0) { s_cnt = cnt; if (blockIdx.x == 0) g_cnt[b] = cnt; }
    }
    __syncthreads();
    const int cnt = s_cnt;

    // ---- trackers
    unsigned bk[L], sk[L];
    float    lmin[L];
    #pragma unroll
    for (int i = 0; i < L; i++) { bk[i] = 0xFFFFFFFFu; sk[i] = 0xFFFFFFFFu; lmin[i] = 3e38f; }
    unsigned r0 = 0x7f800000u, r1 = 0x7f800000u;

    auto body = [&](int k, unsigned& r, int lsh) {
        u64 ntx = s_tp[k * 3 + 0];           // LDS.64 broadcast
        u64 nty = s_tp[k * 3 + 1];
        u64 ntz = s_tp[k * 3 + 2];
        float m4 = 3e38f;
        #pragma unroll
        for (int p = 0; p < 2; p++) {
            u64 dx = add2(cx2[p], ntx);
            u64 dy = add2(cy2[p], nty);
            u64 dz = add2(cz2[p], ntz);
            u64 pd2 = mul2(dz, dz);
            pd2 = fma2(dy, dy, pd2);
            pd2 = fma2(dx, dx, pd2);
            u64 sc = fma2(dz, fzz[p], ff2[p]);
            sc = fma2(dy, fyy[p], sc);
            sc = fma2(dx, fxx[p], sc);
            u64 l2 = add2(pd2, sc);
            float pa, pb, la, lb;
            upk2(pa, pb, pd2);
            upk2(la, lb, l2);
            // no clamp here: ld2 >= 0 up to rounding noise; tiny negatives are
            // harmless in the sum and self-exclude from the u32-ordered REDUX.
            lmin[2*p]   = fminf(lmin[2*p],   la);
            lmin[2*p+1] = fminf(lmin[2*p+1], lb);
            m4 = fminf(m4, fminf(la, lb));
            unsigned ka = (__float_as_uint(pa) & 0xFFFFFFC0u) | (unsigned)k;
            unsigned kb = (__float_as_uint(pb) & 0xFFFFFFC0u) | (unsigned)k;
            unsigned ta = max(ka, bk[2*p]);
            sk[2*p]   = min(sk[2*p], ta);
            bk[2*p]   = min(bk[2*p], ka);
            unsigned tb = max(kb, bk[2*p+1]);
            sk[2*p+1] = min(sk[2*p+1], tb);
            bk[2*p+1] = min(bk[2*p+1], kb);
        }
        unsigned red = __reduce_min_sync(0xffffffffu, __float_as_uint(m4));
        if (lane == k - lsh) r = min(r, red);
    };

    int kend0 = (cnt < 32) ? cnt : 32;
    int k = 0;
    #pragma unroll 2
    for (; k < kend0; k++) body(k, r0, 0);
    #pragma unroll 2
    for (; k < cnt;   k++) body(k, r1, 32);

    atomicMin(&s_g2p[lane],      r0);
    atomicMin(&s_g2p[lane + 32], r1);

    // ---- post-loop: recover ld2 at nn1/nn2 (only for pm landmarks)
    auto ld2_at = [&](int i, int kk) -> float {
        int p = i >> 1, h = i & 1;
        float tx = half_of(s_tp[kk * 3 + 0], 0);  // negated target
        float ty = half_of(s_tp[kk * 3 + 1], 0);
        float tz = half_of(s_tp[kk * 3 + 2], 0);
        float dx = half_of(cx2[p], h) + tx;
        float dy = half_of(cy2[p], h) + ty;
        float dz = half_of(cz2[p], h) + tz;
        float pd2 = fmaf(dx, dx, fmaf(dy, dy, dz * dz));
        float s   = fmaf(dx, half_of(fxx[p], h),
                    fmaf(dy, half_of(fyy[p], h),
                    fmaf(dz, half_of(fzz[p], h), half_of(ff2[p], h))));
        return fmaxf(pd2 + s, 0.f);
    };

    float dl = 0.f, p2g2 = 0.f, sep = 0.f;
    #pragma unroll
    for (int i = 0; i < L; i++) {
        float pd2b = __uint_as_float(bk[i] & 0xFFFFFFC0u);
        float mind = sqrtf(pd2b);
        bool  pm   = mind < 0.1f;
        float tgt  = fminf(mind, 0.2f);
        float diff = d0[i] - tgt;
        float ad   = fabsf(diff);
        float h    = (ad < 1.f) ? 0.5f * diff * diff : (ad - 0.5f);
        dl += val[i] ? h : 0.f;
        if (pm) {
            float l1 = ld2_at(i, (int)(bk[i] & 63u));
            float l2 = ld2_at(i, (int)(sk[i] & 63u));
            p2g2 += fmaxf(lmin[i], 0.f);
            sep  += sqrtf(__fdividef(l1, l2));
        }
    }

    // ---- block reduction
    #pragma unroll
    for (int o = 16; o > 0; o >>= 1) {
        dl   += __shfl_down_sync(0xffffffffu, dl,   o);
        p2g2 += __shfl_down_sync(0xffffffffu, p2g2, o);
        sep  += __shfl_down_sync(0xffffffffu, sep,  o);
    }
    int wid = tid >> 5;
    if (lane == 0) { s_red[wid] = dl; s_red[8 + wid] = p2g2; s_red[16 + wid] = sep; }
    __syncthreads();

    if (tid < KTGT) atomicMin(&g_g2p[b * KTGT + tid], s_g2p[tid]);
    if (tid == 0) {
        float a0 = 0.f, a1 = 0.f, a2 = 0.f;
        #pragma unroll
        for (int i = 0; i < 8; i++) { a0 += s_red[i]; a1 += s_red[8 + i]; a2 += s_red[16 + i]; }
        atomicAdd(&g_dist[b], a0);
        atomicAdd(&g_p2g[b],  a1);
        atomicAdd(&g_sep[b],  a2);
    }

    // ---- last-block finalize (no separate launch)
    __threadfence();
    if (tid == 0) s_last = atomicAdd(&g_ticket, 1u);
    __syncthreads();
    if (s_last == gridDim.x * gridDim.y - 1u) {
        int bb = tid >> 6, kk = tid & 63;
        s_fin[tid] = (kk < g_cnt[bb]) ? __uint_as_float(g_g2p[tid]) : 0.f;
        __syncthreads();
        #pragma unroll
        for (int o = 32; o > 0; o >>= 1) {
            if (kk < o) s_fin[tid] += s_fin[tid + o];
            __syncthreads();
        }
        if (tid == 0) {
            float acc = 0.f;
            #pragma unroll
            for (int bb2 = 0; bb2 < BATCH; bb2++) {
                acc += 0.05f * g_dist[bb2]
                     + 0.05f * (g_p2g[bb2] + s_fin[bb2 * 64])
                     + 0.0005f * ((g_cnt[bb2] >= 2) ? g_sep[bb2] : 0.f);
                g_dist[bb2] = 0.f; g_p2g[bb2] = 0.f; g_sep[bb2] = 0.f;
            }
            out[0] = acc * (1.f / BATCH);
            g_ticket = 0;
        }
        g_g2p[tid] = 0x7f800000u;          // restore pristine for next replay
    }
}

// ---------------- launch ---------------------------------------------------
extern "C" void kernel_launch(void* const* d_in, const int* in_sizes, int n_in,
                              void* d_out, int out_size)
{
    const float* lC      = (const float*)d_in[0];
    const float* lF      = (const float*)d_in[1];
    const float* tC      = (const float*)d_in[2];
    const int*   tF      = (const int*)d_in[3];
    const int*   classes = (const int*)d_in[4];
    int nclass = in_sizes[4];
    int N      = in_sizes[0] / (BATCH * 3);

    dim3 grid((N + TILE - 1) / TILE, BATCH);
    k_main<<<grid, TPB>>>(lC, lF, tC, tF, classes, nclass, N, (float*)d_out);
}